// round 15
// baseline (speedup 1.0000x reference)
#include <cuda_runtime.h>
#include <math.h>

#define Bq 4
#define Nq 512
#define DIN 128
#define F 64
#define NN (Nq*Nq)
#define ALPHA 0.2f
#define MSPLIT 4
#define MCHUNK (Nq/MSPLIT)     // 128
#define NR (Bq*Nq)             // 2048 rows
#define AROWS 4                // rows per A-block

// scratch (plain stores only — everything fully overwritten each run)
__device__ float g_h [NR*F];
__device__ float g_s1[NR];
__device__ float g_t [NR];
__device__ float g_probs[(long)NR*Nq];     // 4MB masked-exp logits
__device__ float g_part[MSPLIT*NR*F];      // AV partials
__device__ float g_psum[MSPLIT*NR];        // row-sum partials

// Streams/events created once, pre-main (before the harness mem checkpoint).
struct GatRes {
    cudaStream_t s2;
    cudaEvent_t eFork, eJoin;
    GatRes() {
        cudaStreamCreateWithFlags(&s2, cudaStreamNonBlocking);
        cudaEventCreateWithFlags(&eFork, cudaEventDisableTiming);
        cudaEventCreateWithFlags(&eJoin, cudaEventDisableTiming);
    }
};
static GatRes g_res;

// ---------------------------------------------------------------------------
// K_S: s1 = x·(W@a1) + b·a1 ; t = x·(W@a2) + b·a2.  Independent of A.
// grid 256 x 256 thr; per-block wa recompute; warp per row.
// ---------------------------------------------------------------------------
__global__ __launch_bounds__(256) void gat_s_kernel(
    const float* __restrict__ x, const float* __restrict__ W,
    const float* __restrict__ bias, const float* __restrict__ a)
{
    __shared__ __align__(16) float as_[2*F];
    __shared__ __align__(16) float wa1s[DIN];
    __shared__ __align__(16) float wa2s[DIN];
    __shared__ float bb[2];

    int tid = threadIdx.x;
    if (tid < 32) ((float4*)as_)[tid] = ((const float4*)a)[tid];
    __syncthreads();

    if (tid < 128) {
        const float4* Wr = (const float4*)(W + (long)tid*F);
        const float4* av = (const float4*)as_;
        float s = 0.f;
        #pragma unroll
        for (int i = 0; i < 16; ++i) {
            float4 w = Wr[i], aa = av[i];
            s += w.x*aa.x + w.y*aa.y + w.z*aa.z + w.w*aa.w;
        }
        wa1s[tid] = s;
        if (tid < 32) {            // warp 0: ba1
            float p = bias[2*tid]*as_[2*tid] + bias[2*tid+1]*as_[2*tid+1];
            #pragma unroll
            for (int o = 16; o; o >>= 1) p += __shfl_xor_sync(0xffffffffu, p, o);
            if (tid == 0) bb[0] = p;
        } else if (tid < 64) {     // warp 1: ba2
            int l = tid - 32;
            float p = bias[2*l]*as_[F+2*l] + bias[2*l+1]*as_[F+2*l+1];
            #pragma unroll
            for (int o = 16; o; o >>= 1) p += __shfl_xor_sync(0xffffffffu, p, o);
            if (l == 0) bb[1] = p;
        }
    } else {
        int k = tid - 128;
        const float4* Wr = (const float4*)(W + (long)k*F);
        const float4* av = (const float4*)(as_ + F);
        float s = 0.f;
        #pragma unroll
        for (int i = 0; i < 16; ++i) {
            float4 w = Wr[i], aa = av[i];
            s += w.x*aa.x + w.y*aa.y + w.z*aa.z + w.w*aa.w;
        }
        wa2s[k] = s;
    }
    __syncthreads();

    int wid = tid >> 5, lane = tid & 31;
    int row = blockIdx.x*8 + wid;
    float4 xv = *(const float4*)(x + (long)row*DIN + lane*4);
    float4 w1 = ((const float4*)wa1s)[lane];
    float4 w2 = ((const float4*)wa2s)[lane];
    float s1 = xv.x*w1.x + xv.y*w1.y + xv.z*w1.z + xv.w*w1.w;
    float t  = xv.x*w2.x + xv.y*w2.y + xv.z*w2.z + xv.w*w2.w;
    #pragma unroll
    for (int o = 16; o; o >>= 1) {
        s1 += __shfl_xor_sync(0xffffffffu, s1, o);
        t  += __shfl_xor_sync(0xffffffffu, t,  o);
    }
    if (lane == 0) { g_s1[row] = s1 + bb[0]; g_t[row] = t + bb[1]; }
}

// ---------------------------------------------------------------------------
// B1: masked exp(leakyrelu(logits)) -> g_probs + psum partials.
// Needs only s1/t. grid 1024 x 256 thr.
// ---------------------------------------------------------------------------
__global__ __launch_bounds__(256) void gat_logits_kernel(const int* __restrict__ adj)
{
    __shared__ float s1s[Nq];
    __shared__ float ts [Nq];

    int tid  = threadIdx.x;
    int lane = tid & 31;
    int wid  = tid >> 5;
    int bid  = blockIdx.x;
    int ms   = bid & 3;
    int rb   = (bid >> 2) & 63;
    int b    = bid >> 8;
    int n0   = rb << 3;
    int m0   = ms * MCHUNK;

    for (int i = tid; i < Nq; i += 256) {
        s1s[i] = g_s1[b*Nq + i];
        ts [i] = g_t [b*Nq + i];
    }
    __syncthreads();

    int n  = n0 + wid;
    int ma = m0 + lane*4;
    const int4 av = *(const int4*)(adj + ((long)b*Nq + n)*Nq + ma);
    int avv[4] = {av.x, av.y, av.z, av.w};
    float4 p4;
    float* pp = (float*)&p4;
    float sum = 0.f;
    #pragma unroll
    for (int j = 0; j < 4; ++j) {
        int m  = ma + j;
        int q1 = 2*(n*Nq + m);
        int idx1 = (q1   < NN) ? (q1   >> 9) : ((q1   - NN) & (Nq-1));
        int idx2 = (q1+1 < NN) ? ((q1+1)>> 9) : ((q1+1 - NN) & (Nq-1));
        float e = s1s[idx1] + ts[idx2];
        e = (e > 0.0f) ? e : ALPHA*e;
        float p = (avv[j] > 0) ? __expf(e) : 0.0f;
        pp[j] = p; sum += p;
    }
    *(float4*)&g_probs[((long)(b*Nq) + n)*Nq + ma] = p4;
    #pragma unroll
    for (int o = 16; o; o >>= 1) sum += __shfl_xor_sync(0xffffffffu, sum, o);
    if (lane == 0) g_psum[(ms*Bq + b)*Nq + n] = sum;
}

// ---------------------------------------------------------------------------
// A: h = x@W + b. R11 fused in-block k-split, s1/t tail removed.
// 1024 thr: thread = (f4, row 0..3, kc 0..15). Grid 512.
// ---------------------------------------------------------------------------
__global__ __launch_bounds__(1024) void gat_h_kernel(
    const float* __restrict__ x, const float* __restrict__ W,
    const float* __restrict__ bias)
{
    __shared__ __align__(16) float4 part[16*AROWS*16];  // 16KB
    __shared__ __align__(16) float xs[AROWS*DIN];       // 2KB

    int tid  = threadIdx.x;
    int f4   = tid & 15;
    int row  = (tid >> 4) & 3;
    int kc   = tid >> 6;
    int row0 = blockIdx.x * AROWS;

    if (tid < AROWS*DIN/4)
        ((float4*)xs)[tid] = ((const float4*)(x + (long)row0*DIN))[tid];
    __syncthreads();

    const float4* W4 = (const float4*)W;
    const float*  xr = xs + row*DIN + kc*8;
    float4 acc = make_float4(0.f, 0.f, 0.f, 0.f);
    #pragma unroll
    for (int k = 0; k < 8; ++k) {
        float4 w  = W4[(kc*8 + k)*16 + f4];
        float  xk = xr[k];
        acc.x += xk*w.x; acc.y += xk*w.y; acc.z += xk*w.z; acc.w += xk*w.w;
    }
    part[kc*(AROWS*16) + row*16 + f4] = acc;
    __syncthreads();

    if (tid < AROWS*16) {
        float4 s = ((const float4*)bias)[tid & 15];
        #pragma unroll
        for (int c = 0; c < 16; ++c) {
            float4 v = part[c*(AROWS*16) + tid];
            s.x += v.x; s.y += v.y; s.z += v.z; s.w += v.w;
        }
        ((float4*)g_h)[(long)(row0 + (tid >> 4))*16 + (tid & 15)] = s;
    }
}

// ---------------------------------------------------------------------------
// B2: partial AV from g_probs + g_h. grid 1024 x 256 thr.
// ---------------------------------------------------------------------------
__global__ __launch_bounds__(256) void gat_av_kernel()
{
    __shared__ __align__(16) float buf[4096];   // red 16KB

    int tid  = threadIdx.x;
    int lane = tid & 31;
    int wid  = tid >> 5;
    int bid  = blockIdx.x;
    int ms   = bid & 3;
    int rb   = (bid >> 2) & 63;
    int b    = bid >> 8;
    int n0   = rb << 3;
    int m0   = ms * MCHUNK;

    float2 acc[8];
    #pragma unroll
    for (int r = 0; r < 8; ++r) acc[r] = make_float2(0.f, 0.f);

    const float2* h2 = (const float2*)(g_h + (long)b*Nq*F);
    #pragma unroll
    for (int kcc = 0; kcc < 4; ++kcc) {
        int mabs = m0 + wid*16 + kcc*4;
        float2 hv0 = h2[(mabs+0)*32 + lane];
        float2 hv1 = h2[(mabs+1)*32 + lane];
        float2 hv2 = h2[(mabs+2)*32 + lane];
        float2 hv3 = h2[(mabs+3)*32 + lane];
        #pragma unroll
        for (int r = 0; r < 8; ++r) {
            float4 p = __ldg((const float4*)&g_probs[((long)(b*Nq) + n0 + r)*Nq + mabs]);
            acc[r].x += p.x*hv0.x + p.y*hv1.x + p.z*hv2.x + p.w*hv3.x;
            acc[r].y += p.x*hv0.y + p.y*hv1.y + p.z*hv2.y + p.w*hv3.y;
        }
    }
    __syncthreads();

    float2* red = (float2*)buf;           // [8 g][8 r][32 f2]
    #pragma unroll
    for (int r = 0; r < 8; ++r)
        red[(wid*8 + r)*32 + lane] = acc[r];
    __syncthreads();

    {
        int r = wid;
        float2 o = make_float2(0.f, 0.f);
        #pragma unroll
        for (int g = 0; g < 8; ++g) {
            float2 v = red[(g*8 + r)*32 + lane];
            o.x += v.x; o.y += v.y;
        }
        ((float2*)g_part)[((long)(ms*Bq + b)*Nq + n0 + r)*32 + lane] = o;
    }
}

// ---------------------------------------------------------------------------
// C: combine + normalize + elu. Coalesced scalar. grid 512 x 256.
// ---------------------------------------------------------------------------
__global__ __launch_bounds__(256) void gat_combine_kernel(float* __restrict__ out)
{
    int gid = blockIdx.x*256 + threadIdx.x;
    int row = gid >> 6;

    float acc = 0.f, s = 0.f;
    #pragma unroll
    for (int ms = 0; ms < MSPLIT; ++ms) {
        acc += g_part[(long)ms*NR*F + gid];
        s   += g_psum[ms*NR + row];
    }
    float v = acc / s;
    out[gid] = (v > 0.0f) ? v : expm1f(v);
}

// ---------------------------------------------------------------------------
extern "C" void kernel_launch(void* const* d_in, const int* in_sizes, int n_in,
                              void* d_out, int out_size)
{
    const float* x    = (const float*)d_in[0];
    const int*   adj  = (const int*)  d_in[1];
    const float* W    = (const float*)d_in[2];
    const float* bias = (const float*)d_in[3];
    const float* a    = (const float*)d_in[4];
    float* out = (float*)d_out;

    // fork: s2 runs K_S -> B1 while stream 0 runs A
    cudaEventRecord(g_res.eFork, 0);
    cudaStreamWaitEvent(g_res.s2, g_res.eFork, 0);

    gat_s_kernel     <<<NR/8, 256, 0, g_res.s2>>>(x, W, bias, a);
    gat_logits_kernel<<<Bq*64*MSPLIT, 256, 0, g_res.s2>>>(adj);
    cudaEventRecord(g_res.eJoin, g_res.s2);

    gat_h_kernel<<<NR/AROWS, 1024>>>(x, W, bias);

    // join, then AV + finalize on stream 0
    cudaStreamWaitEvent(0, g_res.eJoin, 0);
    gat_av_kernel     <<<Bq*64*MSPLIT, 256>>>();
    gat_combine_kernel<<<(NR*F)/256, 256>>>(out);
}

// round 16
// speedup vs baseline: 1.4094x; 1.4094x over previous
#include <cuda_runtime.h>
#include <math.h>

#define Bq 4
#define Nq 512
#define DIN 128
#define F 64
#define NN (Nq*Nq)
#define ALPHA 0.2f
#define MSPLIT 4
#define MCHUNK (Nq/MSPLIT)     // 128
#define NR (Bq*Nq)             // 2048 rows

// scratch (plain stores only)
__device__ float g_h [NR*F];
__device__ float g_s1[NR];
__device__ float g_t [NR];
__device__ float g_part[MSPLIT*NR*F];      // AV partials
__device__ float g_psum[MSPLIT*NR];        // row-sum partials

// ---------------------------------------------------------------------------
// Kernel A: h = x@W + b ; s1 ; t.  W staged in smem (32KB), 8 rows/block,
// 256 thr, grid 256. thread=(f2 0..31, row 0..7); per k: LDS.64 + bcast + 2 FFMA.
// ---------------------------------------------------------------------------
__global__ __launch_bounds__(256) void gat_h_kernel(
    const float* __restrict__ x, const float* __restrict__ W,
    const float* __restrict__ bias, const float* __restrict__ a)
{
    __shared__ __align__(16) float xs[8*DIN];   // 4KB
    __shared__ __align__(16) float Ws[DIN*F];   // 32KB

    int tid  = threadIdx.x;
    int row0 = blockIdx.x * 8;

    // stage x rows (256 float4) and W (2048 float4, 8 per thread)
    ((float4*)xs)[tid] = ((const float4*)(x + (long)row0*DIN))[tid];
    {
        const float4* wsrc = (const float4*)W;
        float4* wdst = (float4*)Ws;
        #pragma unroll
        for (int i = 0; i < 8; ++i)
            wdst[tid + 256*i] = wsrc[tid + 256*i];
    }
    __syncthreads();

    int f2 = tid & 31;                 // float2 feature pair
    int r  = tid >> 5;                 // row 0..7 (= warp id)

    float2 acc = ((const float2*)bias)[f2];
    const float2* Ws2 = (const float2*)Ws;
    const float*  xr  = xs + r*DIN;

    #pragma unroll 8
    for (int k = 0; k < DIN; ++k) {
        float2 w  = Ws2[k*32 + f2];
        float  xk = xr[k];
        acc.x += xk*w.x; acc.y += xk*w.y;
    }

    ((float2*)g_h)[(long)(row0 + r)*32 + f2] = acc;

    // s1/t: full row in one warp -> shuffle reduce
    float2 a1 = ((const float2*)a)[f2];
    float2 a2 = ((const float2*)a)[32 + f2];
    float s1 = acc.x*a1.x + acc.y*a1.y;
    float t  = acc.x*a2.x + acc.y*a2.y;
    #pragma unroll
    for (int o = 16; o; o >>= 1) {
        s1 += __shfl_xor_sync(0xffffffffu, s1, o);
        t  += __shfl_xor_sync(0xffffffffu, t,  o);
    }
    if (f2 == 0) { g_s1[row0 + r] = s1; g_t[row0 + r] = t; }
}

// ---------------------------------------------------------------------------
// Kernel B: 8 rows x 128-m chunk per block. 256 threads, grid 1024.
// Fused: masked exp(leakyrelu(logits)) + row sums + partial AV. (R13 kernel)
// ---------------------------------------------------------------------------
__global__ __launch_bounds__(256) void gat_attn_kernel(const int* __restrict__ adj)
{
    __shared__ float s1s[Nq];
    __shared__ float ts [Nq];
    __shared__ __align__(16) float buf[4096];   // probs[8][128] (4KB) then red (16KB)
    float (*probs)[MCHUNK] = (float(*)[MCHUNK])buf;

    int tid  = threadIdx.x;
    int lane = tid & 31;
    int wid  = tid >> 5;                 // 0..7
    int bid  = blockIdx.x;
    int ms   = bid & 3;
    int rb   = (bid >> 2) & 63;
    int b    = bid >> 8;
    int n0   = rb << 3;
    int m0   = ms * MCHUNK;

    for (int i = tid; i < Nq; i += 256) {
        s1s[i] = g_s1[b*Nq + i];
        ts [i] = g_t [b*Nq + i];
    }
    __syncthreads();

    // ---- phase 1: exp(leakyrelu(logits)) masked, + row partial sums ----
    {
        int n  = n0 + wid;
        int ma = m0 + lane*4;
        const int4 av = *(const int4*)(adj + ((long)b*Nq + n)*Nq + ma);
        int avv[4] = {av.x, av.y, av.z, av.w};
        float4 p4;
        float* pp = (float*)&p4;
        float sum = 0.f;
        #pragma unroll
        for (int j = 0; j < 4; ++j) {
            int m  = ma + j;
            int q1 = 2*(n*Nq + m);
            int idx1 = (q1   < NN) ? (q1   >> 9) : ((q1   - NN) & (Nq-1));
            int idx2 = (q1+1 < NN) ? ((q1+1)>> 9) : ((q1+1 - NN) & (Nq-1));
            float e = s1s[idx1] + ts[idx2];
            e = (e > 0.0f) ? e : ALPHA*e;
            float p = (avv[j] > 0) ? __expf(e) : 0.0f;
            pp[j] = p; sum += p;
        }
        *(float4*)&probs[wid][lane*4] = p4;
        #pragma unroll
        for (int o = 16; o; o >>= 1) sum += __shfl_xor_sync(0xffffffffu, sum, o);
        if (lane == 0) g_psum[(ms*Bq + b)*Nq + n] = sum;
    }
    __syncthreads();

    // ---- phase 2: partial AV. warp = 16 contiguous m, lane = f2 ----
    float2 acc[8];
    #pragma unroll
    for (int r = 0; r < 8; ++r) acc[r] = make_float2(0.f, 0.f);

    const float2* h2 = (const float2*)(g_h + (long)b*Nq*F);
    #pragma unroll
    for (int kcc = 0; kcc < 4; ++kcc) {
        int mloc = wid*16 + kcc*4;
        int mabs = m0 + mloc;
        float2 hv0 = h2[(mabs+0)*32 + lane];
        float2 hv1 = h2[(mabs+1)*32 + lane];
        float2 hv2 = h2[(mabs+2)*32 + lane];
        float2 hv3 = h2[(mabs+3)*32 + lane];
        #pragma unroll
        for (int r = 0; r < 8; ++r) {
            float4 p = *(const float4*)&probs[r][mloc];
            acc[r].x += p.x*hv0.x + p.y*hv1.x + p.z*hv2.x + p.w*hv3.x;
            acc[r].y += p.x*hv0.y + p.y*hv1.y + p.z*hv2.y + p.w*hv3.y;
        }
    }
    __syncthreads();                      // probs dead; buf becomes red (16KB)

    float2* red = (float2*)buf;           // [8 g][8 r][32 f2]
    #pragma unroll
    for (int r = 0; r < 8; ++r)
        red[(wid*8 + r)*32 + lane] = acc[r];
    __syncthreads();

    {
        int r = wid;
        float2 o = make_float2(0.f, 0.f);
        #pragma unroll
        for (int g = 0; g < 8; ++g) {
            float2 v = red[(g*8 + r)*32 + lane];
            o.x += v.x; o.y += v.y;
        }
        ((float2*)g_part)[((long)(ms*Bq + b)*Nq + n0 + r)*32 + lane] = o;
    }
}

// ---------------------------------------------------------------------------
// Kernel C: combine + normalize + elu. Thread = one output element,
// fully coalesced. Grid 512 x 256 thr. (R11/R13 kernel)
// ---------------------------------------------------------------------------
__global__ __launch_bounds__(256) void gat_combine_kernel(float* __restrict__ out)
{
    int gid = blockIdx.x*256 + threadIdx.x;   // 0..131071
    int row = gid >> 6;                       // F=64

    float acc = 0.f, s = 0.f;
    #pragma unroll
    for (int ms = 0; ms < MSPLIT; ++ms) {
        acc += g_part[(long)ms*NR*F + gid];
        s   += g_psum[ms*NR + row];
    }
    float v = acc / s;
    out[gid] = (v > 0.0f) ? v : expm1f(v);
}

// ---------------------------------------------------------------------------
extern "C" void kernel_launch(void* const* d_in, const int* in_sizes, int n_in,
                              void* d_out, int out_size)
{
    const float* x    = (const float*)d_in[0];
    const int*   adj  = (const int*)  d_in[1];
    const float* W    = (const float*)d_in[2];
    const float* bias = (const float*)d_in[3];
    const float* a    = (const float*)d_in[4];
    float* out = (float*)d_out;

    gat_h_kernel<<<NR/8, 256>>>(x, W, bias, a);
    gat_attn_kernel<<<Bq*64*MSPLIT, 256>>>(adj);
    gat_combine_kernel<<<(NR*F)/256, 256>>>(out);
}